// round 4
// baseline (speedup 1.0000x reference)
#include <cuda_runtime.h>

// Problem constants (fixed by setup_inputs)
#define S_LEN   1024
#define D_DIM   32
#define P_STEPS 128
#define L_CHUNK 64
#define NCHUNK  16                  // S_LEN / L_CHUNK
#define RPW     4                   // rows per warp (8 lanes x float4 each)
#define WPB     2                   // warps per block (64 threads)

// out[b,s,d] = sum_{p=0}^{127} alpha*beta^p * x[b, s-1-p, d]
//            + pos_fwd[d] + pos_bwd[ ((s>>5) - d) & 31 ]
// Sliding recurrence: y[s+1] = beta*y[s] + alpha*x[s] - (alpha*beta^128)*x[s-128]
//
// 8 threads per (b,chunk) row, each owning 4 d-channels (float4). A warp covers
// 4 consecutive b with the SAME chunk (chunk warp-uniform). Chunks with
// s0 < P have a partial history window: ntaps = min(s0, 128) warm-up taps and
// no old-tap subtraction in the main loop (window not yet full).
__global__ __launch_bounds__(WPB * 32, 10)
void attn_pred_kernel(const float* __restrict__ x,
                      const float* __restrict__ alpha_p,
                      const float* __restrict__ beta_p,
                      const float* __restrict__ pos_fwd,
                      const float* __restrict__ pos_bwd,
                      float* __restrict__ out)
{
    const int lane  = threadIdx.x & 31;
    const int wg    = blockIdx.x * WPB + (threadIdx.x >> 5);  // global warp id
    const int rgrp  = lane >> 3;       // row inside warp (0..3)
    const int t8    = lane & 7;        // position within row (0..7)
    const int chunk = wg & (NCHUNK - 1);            // warp-uniform
    const int b     = ((wg >> 4) << 2) + rgrp;      // 4 consecutive b per warp
    const int s0    = chunk * L_CHUNK;
    const int d0    = t8 << 2;

    const float alpha = alpha_p[0];
    const float beta  = beta_p[0];
    const float b2 = beta * beta;
    const float b4 = b2 * b2;

    const float4 pf4 = *(const float4*)(pos_fwd + d0);

    const float*  xrow = x + ((size_t)b * S_LEN) * D_DIM + d0;
    const float4* pnew = (const float4*)(xrow + s0 * D_DIM);
    float4*       pout = (float4*)(out + ((size_t)b * S_LEN + s0) * D_DIM + d0);

    // ---- warm-up: y[s0] = sum_{p=0}^{ntaps-1} alpha*beta^p * x[s0-1-p] ----
    // ntaps is warp-uniform: 0 (chunk 0), 64 (chunk 1), or 128 (chunk >= 2).
    const int ntaps = (s0 < P_STEPS) ? s0 : P_STEPS;
    float4 a0 = make_float4(0,0,0,0), a1 = a0, a2v = a0, a3 = a0;
    float wk = alpha;
    const float4* pw = (const float4*)(xrow + (s0 - 1) * D_DIM);
    #pragma unroll 4
    for (int p = 0; p < ntaps; p += 4) {
        const float4 v0 = pw[0];
        const float4 v1 = pw[-1 * (D_DIM / 4)];
        const float4 v2 = pw[-2 * (D_DIM / 4)];
        const float4 v3 = pw[-3 * (D_DIM / 4)];
        a0.x = fmaf(wk, v0.x, a0.x);   a0.y = fmaf(wk, v0.y, a0.y);
        a0.z = fmaf(wk, v0.z, a0.z);   a0.w = fmaf(wk, v0.w, a0.w);
        a1.x = fmaf(wk, v1.x, a1.x);   a1.y = fmaf(wk, v1.y, a1.y);
        a1.z = fmaf(wk, v1.z, a1.z);   a1.w = fmaf(wk, v1.w, a1.w);
        a2v.x = fmaf(wk, v2.x, a2v.x); a2v.y = fmaf(wk, v2.y, a2v.y);
        a2v.z = fmaf(wk, v2.z, a2v.z); a2v.w = fmaf(wk, v2.w, a2v.w);
        a3.x = fmaf(wk, v3.x, a3.x);   a3.y = fmaf(wk, v3.y, a3.y);
        a3.z = fmaf(wk, v3.z, a3.z);   a3.w = fmaf(wk, v3.w, a3.w);
        wk *= b4;
        pw -= 4 * (D_DIM / 4);
    }
    float4 y;
    y.x = fmaf(b2, fmaf(beta, a3.x, a2v.x), fmaf(beta, a1.x, a0.x));
    y.y = fmaf(b2, fmaf(beta, a3.y, a2v.y), fmaf(beta, a1.y, a0.y));
    y.z = fmaf(b2, fmaf(beta, a3.z, a2v.z), fmaf(beta, a1.z, a0.z));
    y.w = fmaf(b2, fmaf(beta, a3.w, a2v.w), fmaf(beta, a1.w, a0.w));
    const float c = wk;                    // alpha * beta^128 when window full

    if (s0 >= P_STEPS) {
        // ---- main loop, full window: old tap always valid ----
        const float4* pold = pnew - P_STEPS * (D_DIM / 4);
        #pragma unroll 1
        for (int grp = 0; grp < L_CHUNK / 32; ++grp) {
            const int gabs = (s0 >> 5) + grp;
            float4 av;
            av.x = pf4.x + __ldg(pos_bwd + ((gabs - d0    ) & 31));
            av.y = pf4.y + __ldg(pos_bwd + ((gabs - d0 - 1) & 31));
            av.z = pf4.z + __ldg(pos_bwd + ((gabs - d0 - 2) & 31));
            av.w = pf4.w + __ldg(pos_bwd + ((gabs - d0 - 3) & 31));
            #pragma unroll
            for (int i = 0; i < 32; ++i) {
                __stcs(pout, make_float4(y.x + av.x, y.y + av.y,
                                         y.z + av.z, y.w + av.w));
                const float4 xn = *pnew;
                const float4 xo = *pold;
                y.x = fmaf(beta, y.x, fmaf(alpha, xn.x, -(c * xo.x)));
                y.y = fmaf(beta, y.y, fmaf(alpha, xn.y, -(c * xo.y)));
                y.z = fmaf(beta, y.z, fmaf(alpha, xn.z, -(c * xo.z)));
                y.w = fmaf(beta, y.w, fmaf(alpha, xn.w, -(c * xo.w)));
                pnew += D_DIM / 4;
                pold += D_DIM / 4;
                pout += D_DIM / 4;
            }
        }
    } else {
        // ---- main loop, window not yet full (s0 + L_CHUNK <= P): no old tap ----
        #pragma unroll 1
        for (int grp = 0; grp < L_CHUNK / 32; ++grp) {
            const int gabs = (s0 >> 5) + grp;
            float4 av;
            av.x = pf4.x + __ldg(pos_bwd + ((gabs - d0    ) & 31));
            av.y = pf4.y + __ldg(pos_bwd + ((gabs - d0 - 1) & 31));
            av.z = pf4.z + __ldg(pos_bwd + ((gabs - d0 - 2) & 31));
            av.w = pf4.w + __ldg(pos_bwd + ((gabs - d0 - 3) & 31));
            #pragma unroll
            for (int i = 0; i < 32; ++i) {
                __stcs(pout, make_float4(y.x + av.x, y.y + av.y,
                                         y.z + av.z, y.w + av.w));
                const float4 xn = *pnew;
                y.x = fmaf(beta, y.x, alpha * xn.x);
                y.y = fmaf(beta, y.y, alpha * xn.y);
                y.z = fmaf(beta, y.z, alpha * xn.z);
                y.w = fmaf(beta, y.w, alpha * xn.w);
                pnew += D_DIM / 4;
                pout += D_DIM / 4;
            }
        }
    }
}

extern "C" void kernel_launch(void* const* d_in, const int* in_sizes, int n_in,
                              void* d_out, int out_size)
{
    const float* x     = (const float*)d_in[0];
    const float* alpha = (const float*)d_in[1];
    const float* beta  = (const float*)d_in[2];
    const float* pf    = (const float*)d_in[3];
    const float* pb    = (const float*)d_in[4];
    // d_in[5] (past_steps) fixed at 128 -> P_STEPS.

    const int B = in_sizes[0] / (S_LEN * D_DIM);        // 1024
    const int n_warps  = (B / RPW) * NCHUNK;            // 4096
    const int n_blocks = n_warps / WPB;                 // 2048

    attn_pred_kernel<<<n_blocks, WPB * 32>>>(x, alpha, beta, pf, pb, (float*)d_out);
}

// round 5
// speedup vs baseline: 1.3095x; 1.3095x over previous
#include <cuda_runtime.h>

// Problem constants (fixed by setup_inputs)
#define S_LEN   1024
#define D_DIM   32
#define P_STEPS 128
#define L_CHUNK 128
#define NCHUNK  8                   // S_LEN / L_CHUNK
#define RPW     4                   // rows per warp (8 lanes x float4 each)
#define WPB     2                   // warps per block (64 threads)
#define F4STR   (D_DIM / 4)         // float4 stride per s-step (8)

// out[b,s,d] = sum_{p=0}^{127} alpha*beta^p * x[b, s-1-p, d]
//            + pos_fwd[d] + pos_bwd[ ((s>>5) - d) & 31 ]
// Sliding recurrence: y[s+1] = beta*y[s] + alpha*x[s] - (alpha*beta^128)*x[s-128]
//
// 8 threads per (b,chunk) row, each owning 4 d-channels (float4); warp covers
// 4 consecutive b with the SAME chunk. Main loop is an explicitly
// double-buffered pipeline (4-step groups) to keep LDG.128s continuously in
// flight around the serial y dependence chain.
__global__ __launch_bounds__(WPB * 32, 8)
void attn_pred_kernel(const float* __restrict__ x,
                      const float* __restrict__ alpha_p,
                      const float* __restrict__ beta_p,
                      const float* __restrict__ pos_fwd,
                      const float* __restrict__ pos_bwd,
                      float* __restrict__ out)
{
    const int lane  = threadIdx.x & 31;
    const int wg    = blockIdx.x * WPB + (threadIdx.x >> 5);
    const int rgrp  = lane >> 3;
    const int t8    = lane & 7;
    const int chunk = wg & (NCHUNK - 1);            // warp-uniform
    const int b     = ((wg >> 3) << 2) + rgrp;      // 4 consecutive b per warp
    const int s0    = chunk * L_CHUNK;
    const int d0    = t8 << 2;

    const float alpha = alpha_p[0];
    const float beta  = beta_p[0];
    const float b2 = beta * beta;
    const float b4 = b2 * b2;

    const float4 pf4 = *(const float4*)(pos_fwd + d0);

    const float*  xrow = x + ((size_t)b * S_LEN) * D_DIM + d0;
    const float4* pnew = (const float4*)(xrow + s0 * D_DIM);
    float4*       pout = (float4*)(out + ((size_t)b * S_LEN + s0) * D_DIM + d0);

    float4 y = make_float4(0.f, 0.f, 0.f, 0.f);

#define STEP_FULL(YV, XN, XO)                                         \
    do {                                                              \
        YV.x = fmaf(beta, YV.x, fmaf(alpha, XN.x, -(c * XO.x)));      \
        YV.y = fmaf(beta, YV.y, fmaf(alpha, XN.y, -(c * XO.y)));      \
        YV.z = fmaf(beta, YV.z, fmaf(alpha, XN.z, -(c * XO.z)));      \
        YV.w = fmaf(beta, YV.w, fmaf(alpha, XN.w, -(c * XO.w)));      \
    } while (0)

#define STEP_NOOLD(YV, XN)                                            \
    do {                                                              \
        YV.x = fmaf(beta, YV.x, alpha * XN.x);                        \
        YV.y = fmaf(beta, YV.y, alpha * XN.y);                        \
        YV.z = fmaf(beta, YV.z, alpha * XN.z);                        \
        YV.w = fmaf(beta, YV.w, alpha * XN.w);                        \
    } while (0)

#define EMIT(STEPIDX, YV)                                             \
    __stcs(pq + (STEPIDX) * F4STR,                                    \
           make_float4(YV.x + av.x, YV.y + av.y, YV.z + av.z, YV.w + av.w))

    if (chunk == 0) {
        // ---- chunk 0: no history, pipelined (new stream only) ----
        #pragma unroll 1
        for (int grp = 0; grp < L_CHUNK / 32; ++grp) {
            const int gabs = grp;
            float4 av;
            av.x = pf4.x + __ldg(pos_bwd + ((gabs - d0    ) & 31));
            av.y = pf4.y + __ldg(pos_bwd + ((gabs - d0 - 1) & 31));
            av.z = pf4.z + __ldg(pos_bwd + ((gabs - d0 - 2) & 31));
            av.w = pf4.w + __ldg(pos_bwd + ((gabs - d0 - 3) & 31));

            const float4* pn = pnew + grp * 32 * F4STR;
            float4*       pq = pout + grp * 32 * F4STR;
            const bool lastg = (grp == L_CHUNK / 32 - 1);

            float4 An[4], Bn[4];
            #pragma unroll
            for (int i = 0; i < 4; ++i) An[i] = pn[i * F4STR];

            #pragma unroll
            for (int g = 0; g < 8; g += 2) {
                const int i1 = (g + 1) * 4;
                int i2 = (g + 2) * 4;
                if (i2 > 28 && lastg) i2 = 28;   // avoid OOB past x end
                #pragma unroll
                for (int i = 0; i < 4; ++i) Bn[i] = pn[(i1 + i) * F4STR];
                #pragma unroll
                for (int i = 0; i < 4; ++i) {
                    EMIT(g * 4 + i, y);
                    STEP_NOOLD(y, An[i]);
                }
                #pragma unroll
                for (int i = 0; i < 4; ++i) An[i] = pn[(i2 + i) * F4STR];
                #pragma unroll
                for (int i = 0; i < 4; ++i) {
                    EMIT(i1 + i, y);
                    STEP_NOOLD(y, Bn[i]);
                }
            }
        }
    } else {
        // ---- warm-up: y[s0] = sum_{p=0}^{127} alpha*beta^p * x[s0-1-p] ----
        const float4* pw = (const float4*)(xrow + (s0 - 1) * D_DIM);
        float4 a0 = make_float4(0,0,0,0), a1 = a0, a2v = a0, a3 = a0;
        float wk = alpha;
        #pragma unroll 4
        for (int p = 0; p < P_STEPS; p += 4) {
            const float4 v0 = pw[0];
            const float4 v1 = pw[-1 * F4STR];
            const float4 v2 = pw[-2 * F4STR];
            const float4 v3 = pw[-3 * F4STR];
            a0.x = fmaf(wk, v0.x, a0.x);   a0.y = fmaf(wk, v0.y, a0.y);
            a0.z = fmaf(wk, v0.z, a0.z);   a0.w = fmaf(wk, v0.w, a0.w);
            a1.x = fmaf(wk, v1.x, a1.x);   a1.y = fmaf(wk, v1.y, a1.y);
            a1.z = fmaf(wk, v1.z, a1.z);   a1.w = fmaf(wk, v1.w, a1.w);
            a2v.x = fmaf(wk, v2.x, a2v.x); a2v.y = fmaf(wk, v2.y, a2v.y);
            a2v.z = fmaf(wk, v2.z, a2v.z); a2v.w = fmaf(wk, v2.w, a2v.w);
            a3.x = fmaf(wk, v3.x, a3.x);   a3.y = fmaf(wk, v3.y, a3.y);
            a3.z = fmaf(wk, v3.z, a3.z);   a3.w = fmaf(wk, v3.w, a3.w);
            wk *= b4;
            pw -= 4 * F4STR;
        }
        y.x = fmaf(b2, fmaf(beta, a3.x, a2v.x), fmaf(beta, a1.x, a0.x));
        y.y = fmaf(b2, fmaf(beta, a3.y, a2v.y), fmaf(beta, a1.y, a0.y));
        y.z = fmaf(b2, fmaf(beta, a3.z, a2v.z), fmaf(beta, a1.z, a0.z));
        y.w = fmaf(b2, fmaf(beta, a3.w, a2v.w), fmaf(beta, a1.w, a0.w));
        const float c = wk;                       // alpha * beta^128

        // ---- main loop: pipelined, both streams ----
        const float4* poldb = pnew - P_STEPS * F4STR;
        #pragma unroll 1
        for (int grp = 0; grp < L_CHUNK / 32; ++grp) {
            const int gabs = (s0 >> 5) + grp;
            float4 av;
            av.x = pf4.x + __ldg(pos_bwd + ((gabs - d0    ) & 31));
            av.y = pf4.y + __ldg(pos_bwd + ((gabs - d0 - 1) & 31));
            av.z = pf4.z + __ldg(pos_bwd + ((gabs - d0 - 2) & 31));
            av.w = pf4.w + __ldg(pos_bwd + ((gabs - d0 - 3) & 31));

            const float4* pn = pnew  + grp * 32 * F4STR;
            const float4* po = poldb + grp * 32 * F4STR;
            float4*       pq = pout  + grp * 32 * F4STR;
            const bool lastg = (grp == L_CHUNK / 32 - 1);

            float4 An[4], Ao[4], Bn[4], Bo[4];
            #pragma unroll
            for (int i = 0; i < 4; ++i) { An[i] = pn[i * F4STR]; Ao[i] = po[i * F4STR]; }

            #pragma unroll
            for (int g = 0; g < 8; g += 2) {
                const int i1 = (g + 1) * 4;
                int i2 = (g + 2) * 4;
                if (i2 > 28 && lastg) i2 = 28;   // avoid OOB past x end
                #pragma unroll
                for (int i = 0; i < 4; ++i) { Bn[i] = pn[(i1 + i) * F4STR]; Bo[i] = po[(i1 + i) * F4STR]; }
                #pragma unroll
                for (int i = 0; i < 4; ++i) {
                    EMIT(g * 4 + i, y);
                    STEP_FULL(y, An[i], Ao[i]);
                }
                #pragma unroll
                for (int i = 0; i < 4; ++i) { An[i] = pn[(i2 + i) * F4STR]; Ao[i] = po[(i2 + i) * F4STR]; }
                #pragma unroll
                for (int i = 0; i < 4; ++i) {
                    EMIT(i1 + i, y);
                    STEP_FULL(y, Bn[i], Bo[i]);
                }
            }
        }
    }
#undef STEP_FULL
#undef STEP_NOOLD
#undef EMIT
}

extern "C" void kernel_launch(void* const* d_in, const int* in_sizes, int n_in,
                              void* d_out, int out_size)
{
    const float* x     = (const float*)d_in[0];
    const float* alpha = (const float*)d_in[1];
    const float* beta  = (const float*)d_in[2];
    const float* pf    = (const float*)d_in[3];
    const float* pb    = (const float*)d_in[4];
    // d_in[5] (past_steps) fixed at 128 -> P_STEPS.

    const int B = in_sizes[0] / (S_LEN * D_DIM);        // 1024
    const int n_warps  = (B / RPW) * NCHUNK;            // 2048
    const int n_blocks = n_warps / WPB;                 // 1024

    attn_pred_kernel<<<n_blocks, WPB * 32>>>(x, alpha, beta, pf, pb, (float*)d_out);
}